// round 8
// baseline (speedup 1.0000x reference)
#include <cuda_runtime.h>
#include <math.h>

#define B_     1024
#define NI_    64
#define NN_    8256
#define E_     131072
#define NOUT_  64
#define MAXP2  128     // pass-2 edges per output node (expected ~16, max ~36)
#define MAXP1  16      // input edges per node (Poisson mean 0.12, max ~6)
#define MAXROW 48      // inline row-mode sources per output node (expected ~2)
#define TPB    1024
#define GRID   128     // GRID*TPB == E_; all blocks co-resident (<=148 SMs)

#define PDL_TRIGGER()  asm volatile("griddepcontrol.launch_dependents;" ::: "memory")
#define PDL_WAIT()     asm volatile("griddepcontrol.wait;" ::: "memory")

// -------- scratch (__device__ globals) --------
__device__ int   g_p2_cnt[NOUT_];
__device__ int   g_p2_src[NOUT_ * MAXP2];
__device__ int   g_p2_e  [NOUT_ * MAXP2];
__device__ int   g_p1_cnt[NN_];
__device__ int   g_p1_src[NN_ * MAXP1];
__device__ int   g_p1_e  [NN_ * MAXP1];
__device__ unsigned char g_has_in[NN_];
__device__ float g_inT[NI_ * B_];            // inputs transposed [feature][batch]

// self-resetting grid barrier (generation counter -> replay-deterministic)
__device__ volatile unsigned g_gen;
__device__ unsigned          g_cnt;

// -------- K1: zero counters only (33 x 256) --------
__global__ void __launch_bounds__(256) k_zero() {
    PDL_TRIGGER();                                     // let k_main schedule now
    int i = blockIdx.x * 256 + threadIdx.x;            // 33*256 = 8448 >= NN_
    if (i < NN_) { g_p1_cnt[i] = 0; g_has_in[i] = 0; }
    if (i < NOUT_) g_p2_cnt[i] = 0;
}

// -------- K2: fused transpose + scan + out; ONE grid barrier --------
__global__ void __launch_bounds__(TPB) k_main(const float* __restrict__ in,
                                              const float* __restrict__ w,
                                              const float* __restrict__ bias,
                                              const float* __restrict__ resp,
                                              const int*   __restrict__ src,
                                              const int*   __restrict__ dst,
                                              float*       __restrict__ out) {
    int blk = blockIdx.x, t = threadIdx.x;

    // ---- pre-wait work: overlaps k_zero entirely ----
    // (1) edge prefetch: exactly one edge per thread (pure inputs)
    int e = blk * TPB + t;
    int d = __ldg(dst + e);
    int s = __ldg(src + e);
    // (2) transpose (blocks 0-15): reads `in`, writes g_inT — neither touched
    //     by k_zero, so it is safe before the wait.
    __shared__ float tile[64][65];
    if (blk < 16) {
        int r0 = blk * 64;
        #pragma unroll
        for (int idx = t; idx < 64 * 64; idx += TPB) {
            int r = idx >> 6, c = idx & 63;            // coalesced load (c fast)
            tile[r][c] = in[(r0 + r) * NI_ + c];
        }
        __syncthreads();
        #pragma unroll
        for (int idx = t; idx < 64 * 64; idx += TPB) {
            int c = idx >> 6, r = idx & 63;            // coalesced store (r fast)
            g_inT[c * B_ + r0 + r] = tile[r][c];
        }
    }

    PDL_WAIT();                                        // counters now zeroed

    // ---- scatter: build edge lists ----
    g_has_in[d] = 1;
    if (d < NOUT_) {                                   // pass-2 edge
        int pos = atomicAdd(&g_p2_cnt[d], 1);
        if (pos < MAXP2) {
            g_p2_src[d * MAXP2 + pos] = s;
            g_p2_e  [d * MAXP2 + pos] = e;
        }
    }
    if (s < NI_) {                                     // pass-1 edge (state0 == 0)
        int pos = atomicAdd(&g_p1_cnt[d], 1);
        if (pos < MAXP1) {
            g_p1_src[d * MAXP1 + pos] = s;
            g_p1_e  [d * MAXP1 + pos] = e;
        }
    }

    // ---- single grid barrier (blocks >= NOUT_ arrive and exit) ----
    __syncthreads();
    if (t == 0) {
        unsigned my = g_gen;
        __threadfence();
        if (atomicAdd(&g_cnt, 1u) == GRID - 1) {
            g_cnt = 0;                                 // reset before release
            __threadfence();
            g_gen = my + 1;                            // release
        } else if (blk < NOUT_) {
            while (g_gen == my) { __nanosleep(32); }
        }
        __threadfence();
    }
    if (blk >= NOUT_) return;
    __syncthreads();

    // ---- out phase: block n computes output node n; thread t = batch t ----
    int n = blk;
    __shared__ int   s_meta[2];
    __shared__ int   s_nd, s_ni;
    __shared__ float s_const;
    __shared__ int   s_dsrc[MAXP2];                    // direct input-feature sources
    __shared__ float s_dw  [MAXP2];
    __shared__ float s_iw[MAXROW];                     // inline row-mode sources
    __shared__ float s_ib[MAXROW];
    __shared__ float s_ir[MAXROW];
    __shared__ int   s_ik[MAXROW];
    __shared__ int   s_isrc[MAXROW * MAXP1];
    __shared__ float s_iew [MAXROW * MAXP1];
    if (t == 0) { s_meta[0] = g_has_in[n]; s_meta[1] = g_p2_cnt[n];
                  s_nd = 0; s_ni = 0; s_const = 0.f; }
    __syncthreads();
    int has = s_meta[0];
    int k = s_meta[1]; if (k > MAXP2) k = MAXP2;
    if (has && t < k) {
        int   sj = g_p2_src[n * MAXP2 + t];
        float wi = w[g_p2_e[n * MAXP2 + t]];
        if (sj < NI_) {
            int pos = atomicAdd(&s_nd, 1);
            s_dsrc[pos] = sj;
            s_dw  [pos] = wi;
        } else {
            int j = sj - NI_;
            if (g_has_in[j]) {
                int k1 = g_p1_cnt[j]; if (k1 > MAXP1) k1 = MAXP1;
                if (k1 == 0) {
                    atomicAdd(&s_const, wi * tanhf(bias[j]));
                } else {
                    int pos = atomicAdd(&s_ni, 1);
                    if (pos < MAXROW) {
                        s_iw[pos] = wi;
                        s_ib[pos] = bias[j];
                        s_ir[pos] = resp[j];
                        s_ik[pos] = k1;
                        for (int q = 0; q < k1; q++) {
                            s_isrc[pos * MAXP1 + q] = g_p1_src[j * MAXP1 + q];
                            s_iew [pos * MAXP1 + q] = w[g_p1_e[j * MAXP1 + q]];
                        }
                    }
                }
            }
            // !has_in[j] -> source value is exactly 0, contributes nothing
        }
    }
    __syncthreads();
    if (!has) { out[t * NOUT_ + n] = 0.f; return; }
    int   nd = s_nd;
    int   ni = s_ni; if (ni > MAXROW) ni = MAXROW;
    float rn = resp[n];
    float bn = fmaf(rn, s_const, bias[n]);             // const sources folded into bias
    float agg = 0.f;
    for (int i = 0; i < nd; i++)                       // direct input-feature sources
        agg = fmaf(s_dw[i], g_inT[s_dsrc[i] * B_ + t], agg);
    for (int i = 0; i < ni; i++) {                     // inline row-mode sources
        int k1 = s_ik[i];
        float a = 0.f;
        for (int q = 0; q < k1; q++)
            a = fmaf(s_iew[i * MAXP1 + q], g_inT[s_isrc[i * MAXP1 + q] * B_ + t], a);
        agg = fmaf(s_iw[i], tanhf(fmaf(s_ir[i], a, s_ib[i])), agg);
    }
    out[t * NOUT_ + n] = tanhf(fmaf(rn, agg, bn));
}

// -------- launch: 2 kernels chained with PDL --------
extern "C" void kernel_launch(void* const* d_in, const int* in_sizes, int n_in,
                              void* d_out, int out_size) {
    const float* inputs  = (const float*)d_in[0];
    const float* weights = (const float*)d_in[1];
    const float* bias    = (const float*)d_in[2];
    const float* resp    = (const float*)d_in[3];
    const int*   src     = (const int*)d_in[4];
    const int*   dst     = (const int*)d_in[5];
    float*       out     = (float*)d_out;

    k_zero<<<33, 256>>>();

    cudaLaunchAttribute at[1];
    at[0].id = cudaLaunchAttributeProgrammaticStreamSerialization;
    at[0].val.programmaticStreamSerializationAllowed = 1;

    cudaLaunchConfig_t cfg{};
    cfg.attrs = at; cfg.numAttrs = 1; cfg.stream = 0;
    cfg.gridDim = dim3(GRID); cfg.blockDim = dim3(TPB);
    cudaLaunchKernelEx(&cfg, k_main, inputs, weights, bias, resp, src, dst, out);
}

// round 9
// speedup vs baseline: 1.0530x; 1.0530x over previous
#include <cuda_runtime.h>
#include <math.h>

#define B_     1024
#define NI_    64
#define NN_    8256
#define E_     131072
#define NOUT_  64
#define MAXP2  128     // pass-2 edges per output node (expected ~16, max ~36)
#define MAXP1  16      // input edges per node (Poisson mean 0.12, max ~6)
#define MAXROW 48      // inline row-mode sources per output node (expected ~2)

#define PDL_TRIGGER()  asm volatile("griddepcontrol.launch_dependents;" ::: "memory")
#define PDL_WAIT()     asm volatile("griddepcontrol.wait;" ::: "memory")

// -------- scratch (__device__ globals, zero at load) --------
// Invariant: counters/flags and g_done/g_ack are ZERO at every kernel_launch
// entry. k_out restores the invariant before the replay ends, so k_scan never
// needs a zeroing predecessor.
__device__ int   g_p2_cnt[NOUT_];
__device__ int   g_p2_src[NOUT_ * MAXP2];
__device__ int   g_p2_e  [NOUT_ * MAXP2];
__device__ int   g_p1_cnt[NN_];
__device__ int   g_p1_src[NN_ * MAXP1];
__device__ int   g_p1_e  [NN_ * MAXP1];
__device__ unsigned char g_has_in[NN_];
__device__ float g_inT[NI_ * B_];            // inputs transposed [feature][batch]
__device__ unsigned g_done;                  // compute blocks that finished GATHER
__device__ unsigned g_ack;                   // resetter completion counter

// -------- K1: edge scatter (blocks 0-511) + transpose (blocks 512-527) --------
__global__ void __launch_bounds__(256) k_scan(const float* __restrict__ in,
                                              const int*   __restrict__ src,
                                              const int*   __restrict__ dst) {
    PDL_TRIGGER();                                     // schedule k_out immediately
    int blk = blockIdx.x, t = threadIdx.x;
    if (blk < 512) {                                   // 512*256 == E_, 1 edge/thread
        int e = blk * 256 + t;
        int d = __ldg(dst + e);
        int s = __ldg(src + e);
        g_has_in[d] = 1;
        if (d < NOUT_) {                               // pass-2 edge
            int pos = atomicAdd(&g_p2_cnt[d], 1);
            if (pos < MAXP2) {
                g_p2_src[d * MAXP2 + pos] = s;
                g_p2_e  [d * MAXP2 + pos] = e;
            }
        }
        if (s < NI_) {                                 // pass-1 edge (state0 == 0)
            int pos = atomicAdd(&g_p1_cnt[d], 1);
            if (pos < MAXP1) {
                g_p1_src[d * MAXP1 + pos] = s;
                g_p1_e  [d * MAXP1 + pos] = e;
            }
        }
    } else {                                           // 16 transpose blocks
        __shared__ float tile[64][65];
        int r0 = (blk - 512) * 64;
        #pragma unroll
        for (int idx = t; idx < 64 * 64; idx += 256) {
            int r = idx >> 6, c = idx & 63;            // coalesced load (c fast)
            tile[r][c] = in[(r0 + r) * NI_ + c];
        }
        __syncthreads();
        #pragma unroll
        for (int idx = t; idx < 64 * 64; idx += 256) {
            int c = idx >> 6, r = idx & 63;            // coalesced store (r fast)
            g_inT[c * B_ + r0 + r] = tile[r][c];
        }
    }
}

// -------- K2: gather+compute (blocks 0-63) | invariant reset (blocks 64-127) --------
__global__ void __launch_bounds__(1024) k_out(const float* __restrict__ w,
                                              const float* __restrict__ bias,
                                              const float* __restrict__ resp,
                                              float* __restrict__ out) {
    int blk = blockIdx.x, t = threadIdx.x;

    if (blk >= NOUT_) {
        // ---- resetter blocks: wait until all 64 compute blocks finished gather ----
        PDL_WAIT();
        if (t == 0) {
            while (*(volatile unsigned*)&g_done < NOUT_) { __nanosleep(64); }
        }
        __syncthreads();
        __threadfence();                               // acquire
        int i = (blk - NOUT_) * 1024 + t;              // 64*1024 = 65536 >= NN_
        if (i < NN_) { g_p1_cnt[i] = 0; g_has_in[i] = 0; }
        if (i < NOUT_) g_p2_cnt[i] = 0;
        __syncthreads();
        if (t == 0) {
            __threadfence();
            unsigned a = atomicAdd(&g_ack, 1u);
            if (a == NOUT_ - 1) {                      // last resetter: restore sync state
                g_done = 0;
                __threadfence();
                g_ack = 0;
            }
        }
        return;
    }

    // ---- compute blocks: node n = blk, thread t = batch element t ----
    int n = blk;
    __shared__ int   s_meta[2];
    __shared__ int   s_nd, s_ni;
    __shared__ float s_const;
    __shared__ int   s_dsrc[MAXP2];                    // direct input-feature sources
    __shared__ float s_dw  [MAXP2];
    __shared__ float s_iw[MAXROW];                     // inline row-mode sources
    __shared__ float s_ib[MAXROW];
    __shared__ float s_ir[MAXROW];
    __shared__ int   s_ik[MAXROW];
    __shared__ int   s_isrc[MAXROW * MAXP1];
    __shared__ float s_iew [MAXROW * MAXP1];
    if (t == 0) { s_nd = 0; s_ni = 0; s_const = 0.f; } // pre-wait smem init
    float rn     = __ldg(resp + n);                    // pure inputs: pre-wait loads
    float bias_n = __ldg(bias + n);
    PDL_WAIT();                                        // scan results now visible
    if (t == 0) { s_meta[0] = g_has_in[n]; s_meta[1] = g_p2_cnt[n]; }
    __syncthreads();
    int has = s_meta[0];
    int k = s_meta[1]; if (k > MAXP2) k = MAXP2;
    if (has && t < k) {
        int   sj = g_p2_src[n * MAXP2 + t];
        float wi = w[g_p2_e[n * MAXP2 + t]];
        if (sj < NI_) {
            int pos = atomicAdd(&s_nd, 1);
            s_dsrc[pos] = sj;
            s_dw  [pos] = wi;
        } else {
            int j = sj - NI_;
            if (g_has_in[j]) {
                int k1 = g_p1_cnt[j]; if (k1 > MAXP1) k1 = MAXP1;
                if (k1 == 0) {
                    atomicAdd(&s_const, wi * tanhf(bias[j]));
                } else {
                    int pos = atomicAdd(&s_ni, 1);
                    if (pos < MAXROW) {
                        s_iw[pos] = wi;
                        s_ib[pos] = bias[j];
                        s_ir[pos] = resp[j];
                        s_ik[pos] = k1;
                        for (int q = 0; q < k1; q++) {
                            s_isrc[pos * MAXP1 + q] = g_p1_src[j * MAXP1 + q];
                            s_iew [pos * MAXP1 + q] = w[g_p1_e[j * MAXP1 + q]];
                        }
                    }
                }
            }
            // !has_in[j] -> source value is exactly 0, contributes nothing
        }
    }
    __syncthreads();
    // all scratch reads done -> release the resetters (overlaps our compute tail)
    if (t == 0) { __threadfence(); atomicAdd(&g_done, 1u); }
    if (!has) { out[t * NOUT_ + n] = 0.f; return; }
    int   nd = s_nd;
    int   ni = s_ni; if (ni > MAXROW) ni = MAXROW;
    float bn = fmaf(rn, s_const, bias_n);              // const sources folded into bias
    float agg = 0.f;
    for (int i = 0; i < nd; i++)                       // direct input-feature sources
        agg = fmaf(s_dw[i], g_inT[s_dsrc[i] * B_ + t], agg);
    for (int i = 0; i < ni; i++) {                     // inline row-mode sources
        int k1 = s_ik[i];
        float a = 0.f;
        for (int q = 0; q < k1; q++)
            a = fmaf(s_iew[i * MAXP1 + q], g_inT[s_isrc[i * MAXP1 + q] * B_ + t], a);
        agg = fmaf(s_iw[i], tanhf(fmaf(s_ir[i], a, s_ib[i])), agg);
    }
    out[t * NOUT_ + n] = tanhf(fmaf(rn, agg, bn));
}

// -------- launch: 2 kernels, PDL-chained --------
extern "C" void kernel_launch(void* const* d_in, const int* in_sizes, int n_in,
                              void* d_out, int out_size) {
    const float* inputs  = (const float*)d_in[0];
    const float* weights = (const float*)d_in[1];
    const float* bias    = (const float*)d_in[2];
    const float* resp    = (const float*)d_in[3];
    const int*   src     = (const int*)d_in[4];
    const int*   dst     = (const int*)d_in[5];
    float*       out     = (float*)d_out;

    k_scan<<<528, 256>>>(inputs, src, dst);

    cudaLaunchAttribute at[1];
    at[0].id = cudaLaunchAttributeProgrammaticStreamSerialization;
    at[0].val.programmaticStreamSerializationAllowed = 1;

    cudaLaunchConfig_t cfg{};
    cfg.attrs = at; cfg.numAttrs = 1; cfg.stream = 0;
    cfg.gridDim = dim3(128); cfg.blockDim = dim3(1024);
    cudaLaunchKernelEx(&cfg, k_out, weights, bias, resp, out);
}

// round 10
// speedup vs baseline: 1.0557x; 1.0025x over previous
#include <cuda_runtime.h>
#include <math.h>

#define B_     1024
#define NI_    64
#define NN_    8256
#define E_     131072
#define NOUT_  64
#define MAXP2  128     // pass-2 edges per output node (expected ~16, max ~36)
#define MAXP1  16      // input edges per node (Poisson mean 0.12)
#define MAXROW 48      // inline row-mode sources per output node (expected ~2)

#define PDL_TRIGGER()  asm volatile("griddepcontrol.launch_dependents;" ::: "memory")
#define PDL_WAIT()     asm volatile("griddepcontrol.wait;" ::: "memory")

// -------- scratch (__device__ globals, zero at load) --------
// Invariant: counters/flags and g_done/g_ack/g_tdone are ZERO at every
// kernel_launch entry; k_out's helper blocks restore it each replay.
__device__ int   g_p2_cnt[NOUT_];
__device__ int   g_p2_src[NOUT_ * MAXP2];
__device__ float g_p2_w  [NOUT_ * MAXP2];
__device__ int   g_p1_cnt[NN_];
__device__ int   g_p1_src[NN_ * MAXP1];
__device__ float g_p1_w  [NN_ * MAXP1];
__device__ unsigned char g_has_in[NN_];
__device__ float g_inT[NI_ * B_];            // inputs transposed [feature][batch]
__device__ unsigned g_tdone;                 // transpose-done counter (16 blocks)
__device__ unsigned g_done;                  // compute blocks done with GATHER
__device__ unsigned g_ack;                   // resetter completion counter

// -------- K1: pure edge scatter, 1 edge/thread (512 x 256) --------
__global__ void __launch_bounds__(256) k_scan(const int*   __restrict__ src,
                                              const int*   __restrict__ dst,
                                              const float* __restrict__ w) {
    PDL_TRIGGER();                                     // schedule k_out immediately
    int e = blockIdx.x * 256 + threadIdx.x;            // 512*256 == E_
    int   d  = __ldg(dst + e);                         // 3 independent coalesced loads
    int   s  = __ldg(src + e);
    float we = __ldg(w + e);
    g_has_in[d] = 1;
    if (d < NOUT_) {                                   // pass-2 edge (store weight now)
        int pos = atomicAdd(&g_p2_cnt[d], 1);
        if (pos < MAXP2) {
            g_p2_src[d * MAXP2 + pos] = s;
            g_p2_w  [d * MAXP2 + pos] = we;
        }
    }
    if (s < NI_) {                                     // pass-1 edge (state0 == 0)
        int pos = atomicAdd(&g_p1_cnt[d], 1);
        if (pos < MAXP1) {
            g_p1_src[d * MAXP1 + pos] = s;
            g_p1_w  [d * MAXP1 + pos] = we;
        }
    }
}

// -------- K2: blocks 0-63 gather+compute | blocks 64-127 transpose + reset --------
__global__ void __launch_bounds__(1024) k_out(const float* __restrict__ in,
                                              const float* __restrict__ bias,
                                              const float* __restrict__ resp,
                                              float* __restrict__ out) {
    int blk = blockIdx.x, t = threadIdx.x;

    if (blk >= NOUT_) {
        // ---- helper blocks ----
        int h = blk - NOUT_;                           // 0..63
        if (h < 16) {
            // transpose tile h: no dependency on k_scan (pre-wait work)
            __shared__ float tile[64][65];
            int r0 = h * 64;
            #pragma unroll
            for (int idx = t; idx < 64 * 64; idx += 1024) {
                int r = idx >> 6, c = idx & 63;        // coalesced load (c fast)
                tile[r][c] = in[(r0 + r) * NI_ + c];
            }
            __syncthreads();
            #pragma unroll
            for (int idx = t; idx < 64 * 64; idx += 1024) {
                int c = idx >> 6, r = idx & 63;        // coalesced store (r fast)
                g_inT[c * B_ + r0 + r] = tile[r][c];
            }
            __syncthreads();
            if (t == 0) { __threadfence(); atomicAdd(&g_tdone, 1u); }
        }
        // wait until all 64 compute blocks finished reading scratch
        if (t == 0) {
            while (*(volatile unsigned*)&g_done < NOUT_) { __nanosleep(64); }
        }
        __syncthreads();
        __threadfence();                               // acquire
        int i = (blk - NOUT_) * 1024 + t;              // 64*1024 >= NN_
        if (i < NN_) { g_p1_cnt[i] = 0; g_has_in[i] = 0; }
        if (i < NOUT_) g_p2_cnt[i] = 0;
        __syncthreads();
        if (t == 0) {
            __threadfence();
            unsigned a = atomicAdd(&g_ack, 1u);
            if (a == NOUT_ - 1) {                      // last acker: restore sync state
                g_done = 0; g_tdone = 0;
                __threadfence();
                g_ack = 0;
            }
        }
        return;
    }

    // ---- compute blocks: node n = blk, thread t = batch element t ----
    int n = blk;
    __shared__ int   s_k;
    __shared__ int   s_nd, s_ni;
    __shared__ float s_const;
    __shared__ int   s_dsrc[MAXP2];                    // direct input-feature sources
    __shared__ float s_dw  [MAXP2];
    __shared__ float s_iw[MAXROW];                     // inline row-mode sources
    __shared__ float s_ib[MAXROW];
    __shared__ float s_ir[MAXROW];
    __shared__ int   s_ik[MAXROW];
    __shared__ int   s_isrc[MAXROW * MAXP1];
    __shared__ float s_iew [MAXROW * MAXP1];
    if (t == 0) { s_nd = 0; s_ni = 0; s_const = 0.f; } // pre-wait smem init
    float rn     = __ldg(resp + n);                    // pure inputs: pre-wait loads
    float bias_n = __ldg(bias + n);
    PDL_WAIT();                                        // scan results now visible
    if (t == 0) s_k = g_p2_cnt[n];
    __syncthreads();
    int k = s_k; if (k > MAXP2) k = MAXP2;             // has_in[n] <=> k > 0
    if (t < k) {
        int   sj = g_p2_src[n * MAXP2 + t];            // level 1 (parallel pair)
        float wi = g_p2_w  [n * MAXP2 + t];
        if (sj < NI_) {
            int pos = atomicAdd(&s_nd, 1);
            s_dsrc[pos] = sj;
            s_dw  [pos] = wi;
        } else {
            int j = sj - NI_;
            if (g_has_in[j]) {                         // level 2 (parallel group)
                int k1 = g_p1_cnt[j]; if (k1 > MAXP1) k1 = MAXP1;
                if (k1 == 0) {
                    atomicAdd(&s_const, wi * tanhf(bias[j]));
                } else {
                    int pos = atomicAdd(&s_ni, 1);
                    if (pos < MAXROW) {
                        s_iw[pos] = wi;
                        s_ib[pos] = bias[j];
                        s_ir[pos] = resp[j];
                        s_ik[pos] = k1;
                        for (int q = 0; q < k1; q++) { // level 3
                            s_isrc[pos * MAXP1 + q] = g_p1_src[j * MAXP1 + q];
                            s_iew [pos * MAXP1 + q] = g_p1_w  [j * MAXP1 + q];
                        }
                    }
                }
            }
            // !has_in[j] -> source value is exactly 0, contributes nothing
        }
    }
    __syncthreads();
    // transpose must be complete before reading g_inT (helpers finish long ago)
    if (t == 0) {
        while (*(volatile unsigned*)&g_tdone < 16u) { __nanosleep(32); }
        __threadfence();                               // acquire g_inT
        atomicAdd(&g_done, 1u);                        // release resetters
    }
    __syncthreads();
    if (k == 0) { out[t * NOUT_ + n] = 0.f; return; }  // no incoming -> exact 0
    int   nd = s_nd;
    int   ni = s_ni; if (ni > MAXROW) ni = MAXROW;
    float bn = fmaf(rn, s_const, bias_n);              // const sources folded into bias
    float agg = 0.f;
    for (int i = 0; i < nd; i++)                       // direct input-feature sources
        agg = fmaf(s_dw[i], g_inT[s_dsrc[i] * B_ + t], agg);
    for (int i = 0; i < ni; i++) {                     // inline row-mode sources
        int k1 = s_ik[i];
        float a = 0.f;
        for (int q = 0; q < k1; q++)
            a = fmaf(s_iew[i * MAXP1 + q], g_inT[s_isrc[i * MAXP1 + q] * B_ + t], a);
        agg = fmaf(s_iw[i], tanhf(fmaf(s_ir[i], a, s_ib[i])), agg);
    }
    out[t * NOUT_ + n] = tanhf(fmaf(rn, agg, bn));
}

// -------- launch: 2 kernels, PDL-chained --------
extern "C" void kernel_launch(void* const* d_in, const int* in_sizes, int n_in,
                              void* d_out, int out_size) {
    const float* inputs  = (const float*)d_in[0];
    const float* weights = (const float*)d_in[1];
    const float* bias    = (const float*)d_in[2];
    const float* resp    = (const float*)d_in[3];
    const int*   src     = (const int*)d_in[4];
    const int*   dst     = (const int*)d_in[5];
    float*       out     = (float*)d_out;

    k_scan<<<512, 256>>>(src, dst, weights);

    cudaLaunchAttribute at[1];
    at[0].id = cudaLaunchAttributeProgrammaticStreamSerialization;
    at[0].val.programmaticStreamSerializationAllowed = 1;

    cudaLaunchConfig_t cfg{};
    cfg.attrs = at; cfg.numAttrs = 1; cfg.stream = 0;
    cfg.gridDim = dim3(128); cfg.blockDim = dim3(1024);
    cudaLaunchKernelEx(&cfg, k_out, inputs, bias, resp, out);
}

// round 11
// speedup vs baseline: 1.0651x; 1.0089x over previous
#include <cuda_runtime.h>
#include <math.h>

#define B_     1024
#define NI_    64
#define NN_    8256
#define E_     131072
#define NOUT_  64
#define MAXP2  128     // pass-2 edges per output node (expected ~16, max ~36)
#define MAXP1  16      // input edges per node (Poisson mean 0.12)
#define MAXROW 48      // inline row-mode sources per output node (expected ~2)
#define TPB    1024
#define GRID   128     // GRID*TPB == E_; all blocks co-resident (128 <= 148 SMs)

// -------- scratch (__device__ globals, zero at load) --------
// Invariant: counters/flags and all sync counters are ZERO at every
// kernel_launch entry; the helper blocks restore it before each replay ends.
__device__ int   g_p2_cnt[NOUT_];
__device__ int   g_p2_src[NOUT_ * MAXP2];
__device__ float g_p2_w  [NOUT_ * MAXP2];
__device__ int   g_p1_cnt[NN_];
__device__ int   g_p1_src[NN_ * MAXP1];
__device__ float g_p1_w  [NN_ * MAXP1];
__device__ unsigned char g_has_in[NN_];
__device__ float g_inT[NI_ * B_];            // inputs transposed [feature][batch]
__device__ volatile unsigned g_gen;          // barrier generation (monotonic)
__device__ unsigned g_cnt;                   // barrier arrivals (self-resets to 0)
__device__ unsigned g_tdone;                 // transpose-done counter (16 blocks)
__device__ unsigned g_done;                  // compute blocks done with GATHER
__device__ unsigned g_ack;                   // resetter completion counter

__global__ void __launch_bounds__(TPB) k_all(const float* __restrict__ in,
                                             const float* __restrict__ w,
                                             const float* __restrict__ bias,
                                             const float* __restrict__ resp,
                                             const int*   __restrict__ src,
                                             const int*   __restrict__ dst,
                                             float*       __restrict__ out) {
    int blk = blockIdx.x, t = threadIdx.x;

    // ---- phase A: every thread scatters exactly one edge (counters pre-zeroed) ----
    {
        int e = blk * TPB + t;
        int   d  = __ldg(dst + e);                     // 3 independent coalesced loads
        int   s  = __ldg(src + e);
        float we = __ldg(w + e);
        g_has_in[d] = 1;
        if (d < NOUT_) {                               // pass-2 edge
            int pos = atomicAdd(&g_p2_cnt[d], 1);
            if (pos < MAXP2) {
                g_p2_src[d * MAXP2 + pos] = s;
                g_p2_w  [d * MAXP2 + pos] = we;
            }
        }
        if (s < NI_) {                                 // pass-1 edge (state0 == 0)
            int pos = atomicAdd(&g_p1_cnt[d], 1);
            if (pos < MAXP1) {
                g_p1_src[d * MAXP1 + pos] = s;
                g_p1_w  [d * MAXP1 + pos] = we;
            }
        }
    }

    // ---- grid barrier: helpers arrive-only; compute blocks spin ----
    __syncthreads();
    if (t == 0) {
        unsigned my = g_gen;
        __threadfence();                               // release scatter stores
        if (atomicAdd(&g_cnt, 1u) == GRID - 1) {
            g_cnt = 0;                                 // reset before release
            __threadfence();
            g_gen = my + 1;                            // release
        } else if (blk < NOUT_) {
            while (g_gen == my) { __nanosleep(32); }
        }
        __threadfence();                               // acquire
    }
    __syncthreads();

    if (blk >= NOUT_) {
        // ---- helper blocks: transpose (16 of them), then reset for next replay ----
        int h = blk - NOUT_;                           // 0..63
        if (h < 16) {
            __shared__ float tile[64][65];
            int r0 = h * 64;
            #pragma unroll
            for (int idx = t; idx < 64 * 64; idx += TPB) {
                int r = idx >> 6, c = idx & 63;        // coalesced load (c fast)
                tile[r][c] = in[(r0 + r) * NI_ + c];
            }
            __syncthreads();
            #pragma unroll
            for (int idx = t; idx < 64 * 64; idx += TPB) {
                int c = idx >> 6, r = idx & 63;        // coalesced store (r fast)
                g_inT[c * B_ + r0 + r] = tile[r][c];
            }
            __syncthreads();
            if (t == 0) { __threadfence(); atomicAdd(&g_tdone, 1u); }
        }
        // wait until all compute blocks finished reading the edge lists
        if (t == 0) {
            while (*(volatile unsigned*)&g_done < NOUT_) { __nanosleep(64); }
        }
        __syncthreads();
        __threadfence();                               // acquire
        int i = h * TPB + t;                           // 64*1024 >= NN_
        if (i < NN_) { g_p1_cnt[i] = 0; g_has_in[i] = 0; }
        if (i < NOUT_) g_p2_cnt[i] = 0;
        __syncthreads();
        if (t == 0) {
            __threadfence();
            unsigned a = atomicAdd(&g_ack, 1u);
            if (a == NOUT_ - 1) {                      // last acker: restore sync state
                g_done = 0; g_tdone = 0;
                __threadfence();
                g_ack = 0;
            }
        }
        return;
    }

    // ---- compute blocks: node n = blk, thread t = batch element t ----
    int n = blk;
    __shared__ int   s_k;
    __shared__ int   s_nd, s_ni;
    __shared__ float s_const;
    __shared__ int   s_dsrc[MAXP2];                    // direct input-feature sources
    __shared__ float s_dw  [MAXP2];
    __shared__ float s_iw[MAXROW];                     // inline row-mode sources
    __shared__ float s_ib[MAXROW];
    __shared__ float s_ir[MAXROW];
    __shared__ int   s_ik[MAXROW];
    __shared__ int   s_isrc[MAXROW * MAXP1];
    __shared__ float s_iew [MAXROW * MAXP1];
    if (t == 0) { s_nd = 0; s_ni = 0; s_const = 0.f; s_k = g_p2_cnt[n]; }
    __syncthreads();
    int k = s_k; if (k > MAXP2) k = MAXP2;             // has_in[n] <=> k > 0
    if (t < k) {
        int   sj = g_p2_src[n * MAXP2 + t];            // level 1
        float wi = g_p2_w  [n * MAXP2 + t];
        if (sj < NI_) {
            int pos = atomicAdd(&s_nd, 1);
            s_dsrc[pos] = sj;
            s_dw  [pos] = wi;
        } else {
            int j = sj - NI_;
            if (g_has_in[j]) {                         // level 2
                int k1 = g_p1_cnt[j]; if (k1 > MAXP1) k1 = MAXP1;
                if (k1 == 0) {
                    atomicAdd(&s_const, wi * tanhf(bias[j]));
                } else {
                    int pos = atomicAdd(&s_ni, 1);
                    if (pos < MAXROW) {
                        s_iw[pos] = wi;
                        s_ib[pos] = bias[j];
                        s_ir[pos] = resp[j];
                        s_ik[pos] = k1;
                        for (int q = 0; q < k1; q++) { // level 3
                            s_isrc[pos * MAXP1 + q] = g_p1_src[j * MAXP1 + q];
                            s_iew [pos * MAXP1 + q] = g_p1_w  [j * MAXP1 + q];
                        }
                    }
                }
            }
            // !has_in[j] -> source value is exactly 0, contributes nothing
        }
    }
    __syncthreads();
    // gather done -> release resetters; ensure transpose complete before g_inT reads
    if (t == 0) {
        __threadfence();
        atomicAdd(&g_done, 1u);
        while (*(volatile unsigned*)&g_tdone < 16u) { __nanosleep(32); }
        __threadfence();                               // acquire g_inT
    }
    __syncthreads();
    float rn = resp[n];
    if (k == 0) { out[t * NOUT_ + n] = 0.f; return; }  // no incoming -> exact 0
    int   nd = s_nd;
    int   ni = s_ni; if (ni > MAXROW) ni = MAXROW;
    float bn = fmaf(rn, s_const, bias[n]);             // const sources folded into bias
    float agg = 0.f;
    for (int i = 0; i < nd; i++)                       // direct input-feature sources
        agg = fmaf(s_dw[i], g_inT[s_dsrc[i] * B_ + t], agg);
    for (int i = 0; i < ni; i++) {                     // inline row-mode sources
        int k1 = s_ik[i];
        float a = 0.f;
        for (int q = 0; q < k1; q++)
            a = fmaf(s_iew[i * MAXP1 + q], g_inT[s_isrc[i * MAXP1 + q] * B_ + t], a);
        agg = fmaf(s_iw[i], tanhf(fmaf(s_ir[i], a, s_ib[i])), agg);
    }
    out[t * NOUT_ + n] = tanhf(fmaf(rn, agg, bn));
}

// -------- launch: ONE kernel, no predecessors --------
extern "C" void kernel_launch(void* const* d_in, const int* in_sizes, int n_in,
                              void* d_out, int out_size) {
    const float* inputs  = (const float*)d_in[0];
    const float* weights = (const float*)d_in[1];
    const float* bias    = (const float*)d_in[2];
    const float* resp    = (const float*)d_in[3];
    const int*   src     = (const int*)d_in[4];
    const int*   dst     = (const int*)d_in[5];
    float*       out     = (float*)d_out;

    k_all<<<GRID, TPB>>>(inputs, weights, bias, resp, src, dst, out);
}